// round 15
// baseline (speedup 1.0000x reference)
#include <cuda_runtime.h>
#include <cstdint>
#include <math.h>

#define B_  128
#define T_  256
#define D_  256
#define U_  256
#define NG  768
#define M_  (B_ * T_)

typedef unsigned long long u64;

__device__ float g_xz[M_ * NG];        // x@kernel + bias
__device__ float g_subo[3 * B_ * T_];  // sub_out[s][b][t]

// ---------------- helpers ------------------------------------------------
__device__ __forceinline__ u64 pack2(float lo, float hi) {
    u64 r;
    asm("mov.b64 %0, {%1, %2};" : "=l"(r)
        : "r"(__float_as_uint(lo)), "r"(__float_as_uint(hi)));
    return r;
}
__device__ __forceinline__ u64 fma2(u64 a, u64 b, u64 c) {
    u64 d;
    asm("fma.rn.f32x2 %0, %1, %2, %3;" : "=l"(d) : "l"(a), "l"(b), "l"(c));
    return d;
}
__device__ __forceinline__ float2 unpack2(u64 v) {
    uint32_t lo, hi;
    asm("mov.b64 {%0, %1}, %2;" : "=r"(lo), "=r"(hi) : "l"(v));
    return make_float2(__uint_as_float(lo), __uint_as_float(hi));
}
__device__ __forceinline__ uint32_t smem_u32(const void* p) {
    uint32_t a;
    asm("{ .reg .u64 t; cvta.to.shared.u64 t, %1; cvt.u32.u64 %0, t; }"
        : "=r"(a) : "l"(p));
    return a;
}
__device__ __forceinline__ void mbar_init(uint32_t m, uint32_t cnt) {
    asm volatile("mbarrier.init.shared.b64 [%0], %1;" :: "r"(m), "r"(cnt) : "memory");
}
__device__ __forceinline__ void mbar_arm(uint32_t m, uint32_t bytes) {
    asm volatile("mbarrier.arrive.expect_tx.shared.b64 _, [%0], %1;"
                 :: "r"(m), "r"(bytes) : "memory");
}
__device__ __forceinline__ void mbar_wait(uint32_t m, uint32_t parity) {
    asm volatile(
        "{\n\t"
        ".reg .pred P;\n\t"
        "WL%=:\n\t"
        "mbarrier.try_wait.parity.acquire.cta.shared::cta.b64 P, [%0], %1, 0x989680;\n\t"
        "@P bra WD%=;\n\t"
        "bra WL%=;\n\t"
        "WD%=:\n\t"
        "}"
        :: "r"(m), "r"(parity) : "memory");
}
__device__ __forceinline__ uint32_t mapa_u32(uint32_t laddr, int rank) {
    uint32_t r;
    asm("mapa.shared::cluster.u32 %0, %1, %2;" : "=r"(r) : "r"(laddr), "r"(rank));
    return r;
}
// bulk smem -> remote smem copy, completes remote mbarrier with tx bytes
__device__ __forceinline__ void bulk_to(uint32_t dst_remote, uint32_t src_local,
                                        uint32_t bytes, uint32_t mbar_remote) {
    asm volatile(
        "cp.async.bulk.shared::cluster.shared::cta.mbarrier::complete_tx::bytes "
        "[%0], [%1], %2, [%3];"
        :: "r"(dst_remote), "r"(src_local), "r"(bytes), "r"(mbar_remote) : "memory");
}
// fast transcendentals (MUFU-based; rel err ~1e-6, far under 1e-3 budget)
__device__ __forceinline__ float fast_sig(float x) {
    return __fdividef(1.f, 1.f + __expf(-x));
}
__device__ __forceinline__ float fast_tanh(float x) {
    return 1.f - __fdividef(2.f, __expf(2.f * x) + 1.f);
}

// ---------------------------------------------------------------- k1: GEMM (R11 version)
__global__ __launch_bounds__(256, 2) void k1_gemm(const float* __restrict__ x,
                                                  const float* __restrict__ w,
                                                  const float* __restrict__ bias) {
    __shared__ __align__(16) float As[2][8][132];
    __shared__ __align__(16) float Bs[2][8][128];
    const int tid = threadIdx.x;
    const int n0 = blockIdx.x * 128, m0 = blockIdx.y * 128;
    const int tm = (tid >> 4) * 8, tn = (tid & 15) * 8;
    const int mA = tid >> 1, kq = (tid & 1) * 4;
    const int rB = tid >> 5, cB = (tid & 31) * 4;

    u64 acc2[4][8];
#pragma unroll
    for (int p = 0; p < 4; p++)
#pragma unroll
        for (int j = 0; j < 8; j++) acc2[p][j] = 0ull;

    float4 av = *reinterpret_cast<const float4*>(&x[(m0 + mA) * 256 + kq]);
    float4 bv = *reinterpret_cast<const float4*>(&w[rB * NG + n0 + cB]);

    for (int k0 = 0; k0 < 256; k0 += 8) {
        const int cur = (k0 >> 3) & 1;
        As[cur][kq + 0][mA] = av.x; As[cur][kq + 1][mA] = av.y;
        As[cur][kq + 2][mA] = av.z; As[cur][kq + 3][mA] = av.w;
        *reinterpret_cast<float4*>(&Bs[cur][rB][cB]) = bv;
        __syncthreads();
        if (k0 + 8 < 256) {
            av = *reinterpret_cast<const float4*>(&x[(m0 + mA) * 256 + k0 + 8 + kq]);
            bv = *reinterpret_cast<const float4*>(&w[(k0 + 8 + rB) * NG + n0 + cB]);
        }
#pragma unroll
        for (int k = 0; k < 8; k++) {
            const ulonglong2* ap = reinterpret_cast<const ulonglong2*>(&As[cur][k][tm]);
            const ulonglong2 aA = ap[0], aB = ap[1];
            const u64 a2[4] = {aA.x, aA.y, aB.x, aB.y};
            float b[8];
            *reinterpret_cast<float4*>(b)     = *reinterpret_cast<float4*>(&Bs[cur][k][tn]);
            *reinterpret_cast<float4*>(b + 4) = *reinterpret_cast<float4*>(&Bs[cur][k][tn + 4]);
            u64 b2[8];
#pragma unroll
            for (int j = 0; j < 8; j++) b2[j] = pack2(b[j], b[j]);
#pragma unroll
            for (int p = 0; p < 4; p++)
#pragma unroll
                for (int j = 0; j < 8; j++) acc2[p][j] = fma2(a2[p], b2[j], acc2[p][j]);
        }
    }
    float bi[8];
    *reinterpret_cast<float4*>(bi)     = *reinterpret_cast<const float4*>(&bias[n0 + tn]);
    *reinterpret_cast<float4*>(bi + 4) = *reinterpret_cast<const float4*>(&bias[n0 + tn + 4]);
#pragma unroll
    for (int p = 0; p < 4; p++) {
        float r0[8], r1[8];
#pragma unroll
        for (int j = 0; j < 8; j++) {
            float2 v = unpack2(acc2[p][j]);
            r0[j] = v.x + bi[j];
            r1[j] = v.y + bi[j];
        }
        float* d0 = &g_xz[(size_t)(m0 + tm + 2 * p) * NG + n0 + tn];
        float* d1 = d0 + NG;
#pragma unroll
        for (int j = 0; j < 8; j++) { d0[j] = r0[j]; d1[j] = r1[j]; }
    }
}

// ---------------------------------------------------------------- k2: sub-TKAN/KAN
__global__ __launch_bounds__(256) void k2_sub(const float* __restrict__ x,
                                              const float* __restrict__ stk,
                                              const float* __restrict__ srk,
                                              const float* __restrict__ kbw,
                                              const float* __restrict__ ksw) {
    __shared__ float sw[256 * 9];
    __shared__ float wpart[8];
    __shared__ float bcast;
    const int s = blockIdx.x >> 7, b = blockIdx.x & 127;
    const int d = threadIdx.x, lane = d & 31, wid = d >> 5;

    const float skx = srk[s * 512 + d];
    const float skh = srk[s * 512 + 256 + d];
    const float bw  = kbw[s * 256 + d];
    const float rh  = stk[s * 2 + 0];
    const float rx  = stk[s * 2 + 1];
#pragma unroll
    for (int c = 0; c < 8; c++) sw[d * 9 + c] = ksw[(s * 256 + d) * 8 + c];
    __syncthreads();

    float sub = 0.f;
    const float* xp = x + (b * T_) * D_ + d;
    float* so = g_subo + (s * B_ + b) * T_;

    float xv = __ldg(&xp[0]);
    for (int t = 0; t < T_; t++) {
        const float xn = (t < T_ - 1) ? __ldg(&xp[(t + 1) * D_]) : 0.f;
        const float v = xv * skx + sub * skh;
        float e = v * fast_sig(v) * bw;
        const float xg = (v + 2.2f) * 2.5f;
        const float fj = floorf(xg);
        const int j = (int)fj;
        if (j >= 0 && j <= 10) {
            const float wl = xg - fj, w2 = wl * wl, w3 = w2 * wl;
            const float omw = 1.f - wl;
            const float n0 = (1.f / 6.f) * omw * omw * omw;
            const float n1 = (1.f / 6.f) * (3.f * w3 - 6.f * w2 + 4.f);
            const float n2 = (1.f / 6.f) * (-3.f * w3 + 3.f * w2 + 3.f * wl + 1.f);
            const float n3 = (1.f / 6.f) * w3;
            const int c0 = j - 3;
            const float* swd = &sw[d * 9];
            if (c0     >= 0 && c0     < 8) e += n0 * swd[c0];
            if (c0 + 1 >= 0 && c0 + 1 < 8) e += n1 * swd[c0 + 1];
            if (c0 + 2 >= 0 && c0 + 2 < 8) e += n2 * swd[c0 + 2];
            if (c0 + 3 >= 0 && c0 + 3 < 8) e += n3 * swd[c0 + 3];
        }
#pragma unroll
        for (int off = 16; off > 0; off >>= 1) e += __shfl_xor_sync(0xffffffffu, e, off);
        if (lane == 0) wpart[wid] = e;
        __syncthreads();
        if (d == 0) {
            float tot = 0.f;
#pragma unroll
            for (int ww = 0; ww < 8; ww++) tot += wpart[ww];
            so[t] = tot;
            bcast = rh * tot + rx * sub;
        }
        __syncthreads();
        sub = bcast;
        xv = xn;
    }
}

// ---------------------------------------------------------------- k3: recurrence
// 128 CTAs x 512 threads, cluster 8 (= 8 batches; rank = 32-u tile).
// Exchange: each gate warp STS's its 128-B h-row locally (own copy), then
// lane 0 bulk-copies that row to the 7 peer ranks (cp.async.bulk, 128 B,
// remote complete_tx). 56 received messages/step instead of 1024 -> kills
// the per-message mbar RMW serialization. No extra CTA barrier on the path.
__global__ __launch_bounds__(512, 1) __cluster_dims__(8, 1, 1)
void k3_rnn(const float* __restrict__ rk,   // (256,768)
            const float* __restrict__ aw,   // (3,256)
            const float* __restrict__ ab,   // (256)
            float* __restrict__ out) {      // (B,T,U)
    __shared__ __align__(16) float hs[2][2048];      // [buf][b_local*256 + u]
    __shared__ __align__(16) float red[256 * 52];    // stride 52: conflict-free + 16B aligned
    __shared__ __align__(8) unsigned long long mbar_s[2];
    const int tid = threadIdx.x;
    const int wid = tid >> 5, lane = tid & 31;
    const int rank_self = blockIdx.x & 7;
    const int u0 = rank_self * 32;
    const int b0 = (blockIdx.x >> 3) * 8;
    const int k0 = wid * 16;

    const uint32_t mb0 = smem_u32(&mbar_s[0]);
    const uint32_t mb1 = smem_u32(&mbar_s[1]);

    // weights: 16 k per warp, packed in pairs along k (once)
    u64 wi2[8], wf2[8], wc2[8];
#pragma unroll
    for (int kk = 0; kk < 8; kk++) {
        const int r0 = (k0 + 2 * kk) * NG + u0 + lane;
        const int r1 = r0 + NG;
        wi2[kk] = pack2(rk[r0],       rk[r1]);
        wf2[kk] = pack2(rk[r0 + 256], rk[r1 + 256]);
        wc2[kk] = pack2(rk[r0 + 512], rk[r1 + 512]);
    }
    // gate-role constants (warps 0-7): thread owns cell (b = b0+wid, u = u0+lane)
    const int gb = b0 + (wid & 7);
    const int gu = u0 + lane;
    const float aw0 = aw[gu], aw1 = aw[256 + gu], aw2 = aw[512 + gu];
    const float abr = ab[gu];
    const float* so0 = g_subo + (0 * B_ + gb) * T_;
    const float* so1 = g_subo + (1 * B_ + gb) * T_;
    const float* so2 = g_subo + (2 * B_ + gb) * T_;
    const float* xzp = g_xz + (size_t)(gb * T_) * NG + gu;
    float* yp = out + (size_t)(gb * T_) * U_ + gu;

    // gate warp wid produces row hs[buf][wid*256 + u0 .. +32) = 128 B
    const uint32_t lrow = smem_u32(&hs[0][(wid & 7) * 256 + u0]);
    uint32_t rrow[8], rmb[8];
#pragma unroll
    for (int r = 0; r < 8; r++) {
        rrow[r] = mapa_u32(lrow, r);
        rmb[r]  = mapa_u32(mb0, r);
    }

    if (tid == 0) {
        mbar_init(mb0, 1);
        mbar_init(mb1, 1);
        mbar_arm(mb0, 7168);   // 7 sources x 8 rows x 128 B
        mbar_arm(mb1, 7168);
    }
    for (int i = tid; i < 2048; i += 512) hs[0][i] = 0.f;
    __syncthreads();
    asm volatile("barrier.cluster.arrive.aligned;\n\t"
                 "barrier.cluster.wait.aligned;" ::: "memory");

    // prefetch gate inputs for t=0
    float xz0, xz1, xz2, s0, s1, s2;
    if (wid < 8) {
        xz0 = __ldg(&xzp[0]);
        xz1 = __ldg(&xzp[256]);
        xz2 = __ldg(&xzp[512]);
        s0 = __ldg(&so0[0]); s1 = __ldg(&so1[0]); s2 = __ldg(&so2[0]);
    }

    float c = 0.f;
    for (int t = 0; t < T_; t++) {
        const int p = t & 1;
        if (t > 0) {
            const uint32_t m = p ? mb1 : mb0;
            mbar_wait(m, ((t - 1) >> 1) & 1);
            if (tid == 0) mbar_arm(m, 7168);   // re-arm before our sends this step
        }

        // compute role: all 16 warps; h pairs from LDS.128 halves (broadcast)
#pragma unroll
        for (int b = 0; b < 8; b++) {
            u64 ai = 0ull, af = 0ull, ac = 0ull;
            const ulonglong2* hp =
                reinterpret_cast<const ulonglong2*>(&hs[p][b * 256 + k0]);
            const ulonglong2 h0 = hp[0], h1 = hp[1];
            ai = fma2(h0.x, wi2[0], ai); af = fma2(h0.x, wf2[0], af); ac = fma2(h0.x, wc2[0], ac);
            ai = fma2(h0.y, wi2[1], ai); af = fma2(h0.y, wf2[1], af); ac = fma2(h0.y, wc2[1], ac);
            ai = fma2(h1.x, wi2[2], ai); af = fma2(h1.x, wf2[2], af); ac = fma2(h1.x, wc2[2], ac);
            ai = fma2(h1.y, wi2[3], ai); af = fma2(h1.y, wf2[3], af); ac = fma2(h1.y, wc2[3], ac);
            const ulonglong2 h2 = hp[2], h3 = hp[3];
            ai = fma2(h2.x, wi2[4], ai); af = fma2(h2.x, wf2[4], af); ac = fma2(h2.x, wc2[4], ac);
            ai = fma2(h2.y, wi2[5], ai); af = fma2(h2.y, wf2[5], af); ac = fma2(h2.y, wc2[5], ac);
            ai = fma2(h3.x, wi2[6], ai); af = fma2(h3.x, wf2[6], af); ac = fma2(h3.x, wc2[6], ac);
            ai = fma2(h3.y, wi2[7], ai); af = fma2(h3.y, wf2[7], af); ac = fma2(h3.y, wc2[7], ac);
            const float2 vi = unpack2(ai), vf = unpack2(af), vc = unpack2(ac);
            const int base = (b * 32 + lane) * 52 + wid;
            red[base]      = vi.x + vi.y;
            red[base + 16] = vf.x + vf.y;
            red[base + 32] = vc.x + vc.y;
        }
        __syncthreads();   // S1: red complete (also: all compute reads of hs done)

        // gate role: warps 0-7
        if (wid < 8) {
            const int rbase = (wid * 32 + lane) * 52;
            const float4* rp = reinterpret_cast<const float4*>(&red[rbase]);
            float4 q0 = rp[0], q1 = rp[1], q2 = rp[2], q3 = rp[3];
            float zi = xz0 + (q0.x + q0.y + q0.z + q0.w) + (q1.x + q1.y + q1.z + q1.w)
                           + (q2.x + q2.y + q2.z + q2.w) + (q3.x + q3.y + q3.z + q3.w);
            q0 = rp[4]; q1 = rp[5]; q2 = rp[6]; q3 = rp[7];
            float zf = xz1 + (q0.x + q0.y + q0.z + q0.w) + (q1.x + q1.y + q1.z + q1.w)
                           + (q2.x + q2.y + q2.z + q2.w) + (q3.x + q3.y + q3.z + q3.w);
            q0 = rp[8]; q1 = rp[9]; q2 = rp[10]; q3 = rp[11];
            float zc = xz2 + (q0.x + q0.y + q0.z + q0.w) + (q1.x + q1.y + q1.z + q1.w)
                           + (q2.x + q2.y + q2.z + q2.w) + (q3.x + q3.y + q3.z + q3.w);

            const float ig = fast_sig(zi);
            const float fg = fast_sig(zf);
            c = fg * c + ig * fast_tanh(zc);
            const float o = fast_sig(s0 * aw0 + s1 * aw1 + s2 * aw2 + abr);
            const float h = o * fast_tanh(c);

            if (t < T_ - 1) {
                // own copy via STS into next buffer, then bulk to 7 peers
                const uint32_t doff = p ? 0u : 8192u;   // hs[p^1] byte offset
                hs[p ^ 1][wid * 256 + u0 + lane] = h;
                __syncwarp();
                if (lane == 0) {
                    asm volatile("fence.proxy.async.shared::cta;" ::: "memory");
                    const uint32_t moff = p ? 0u : 8u;  // mb0 / mb1
#pragma unroll
                    for (int r = 0; r < 8; r++)
                        if (r != rank_self)
                            bulk_to(rrow[r] + doff, lrow + doff, 128u, rmb[r] + moff);
                }
            }
            yp[(size_t)t * U_] = h;

            if (t < T_ - 1) {   // prefetch next step's gate inputs
                const size_t o1 = (size_t)(t + 1) * NG;
                xz0 = __ldg(&xzp[o1]);
                xz1 = __ldg(&xzp[o1 + 256]);
                xz2 = __ldg(&xzp[o1 + 512]);
                s0 = __ldg(&so0[t + 1]); s1 = __ldg(&so1[t + 1]); s2 = __ldg(&so2[t + 1]);
            }
        }
        __syncthreads();   // S2: gate red-reads & own-row STS precede next step
    }
    asm volatile("barrier.cluster.arrive.aligned;\n\t"
                 "barrier.cluster.wait.aligned;" ::: "memory");
}

// ---------------------------------------------------------------- launch
extern "C" void kernel_launch(void* const* d_in, const int* in_sizes, int n_in,
                              void* d_out, int out_size) {
    const float* x    = (const float*)d_in[0];
    const float* ker  = (const float*)d_in[1];
    const float* rk   = (const float*)d_in[2];
    const float* bias = (const float*)d_in[3];
    const float* stk  = (const float*)d_in[4];
    const float* srk  = (const float*)d_in[5];
    const float* aw   = (const float*)d_in[6];
    const float* ab   = (const float*)d_in[7];
    const float* kbw  = (const float*)d_in[8];
    const float* ksw  = (const float*)d_in[9];
    float* out = (float*)d_out;

    // fork k2 onto a side stream so it overlaps k1 (both feed k3)
    static cudaStream_t s2 = nullptr;
    static cudaEvent_t ev1 = nullptr, ev2 = nullptr;
    if (s2 == nullptr) {
        cudaStreamCreateWithFlags(&s2, cudaStreamNonBlocking);
        cudaEventCreateWithFlags(&ev1, cudaEventDisableTiming);
        cudaEventCreateWithFlags(&ev2, cudaEventDisableTiming);
    }
    cudaEventRecord(ev1, 0);
    cudaStreamWaitEvent(s2, ev1, 0);
    k2_sub<<<3 * B_, 256, 0, s2>>>(x, stk, srk, kbw, ksw);
    cudaEventRecord(ev2, s2);
    k1_gemm<<<dim3(NG / 128, M_ / 128), 256>>>(x, ker, bias);
    cudaStreamWaitEvent(0, ev2, 0);
    k3_rnn<<<128, 512>>>(rk, aw, ab, out);
}

// round 16
// speedup vs baseline: 1.0332x; 1.0332x over previous
#include <cuda_runtime.h>
#include <cstdint>
#include <math.h>

#define B_  128
#define T_  256
#define D_  256
#define U_  256
#define NG  768
#define M_  (B_ * T_)

typedef unsigned long long u64;

__device__ float g_xz[M_ * NG];        // x@kernel + bias
__device__ float g_subo[3 * B_ * T_];  // sub_out[s][b][t]

// ---------------- helpers ------------------------------------------------
__device__ __forceinline__ u64 pack2(float lo, float hi) {
    u64 r;
    asm("mov.b64 %0, {%1, %2};" : "=l"(r)
        : "r"(__float_as_uint(lo)), "r"(__float_as_uint(hi)));
    return r;
}
__device__ __forceinline__ u64 fma2(u64 a, u64 b, u64 c) {
    u64 d;
    asm("fma.rn.f32x2 %0, %1, %2, %3;" : "=l"(d) : "l"(a), "l"(b), "l"(c));
    return d;
}
__device__ __forceinline__ float2 unpack2(u64 v) {
    uint32_t lo, hi;
    asm("mov.b64 {%0, %1}, %2;" : "=r"(lo), "=r"(hi) : "l"(v));
    return make_float2(__uint_as_float(lo), __uint_as_float(hi));
}
__device__ __forceinline__ uint32_t smem_u32(const void* p) {
    uint32_t a;
    asm("{ .reg .u64 t; cvta.to.shared.u64 t, %1; cvt.u32.u64 %0, t; }"
        : "=r"(a) : "l"(p));
    return a;
}
__device__ __forceinline__ void mbar_init(uint32_t m, uint32_t cnt) {
    asm volatile("mbarrier.init.shared.b64 [%0], %1;" :: "r"(m), "r"(cnt) : "memory");
}
__device__ __forceinline__ void mbar_arm(uint32_t m, uint32_t bytes) {
    asm volatile("mbarrier.arrive.expect_tx.shared.b64 _, [%0], %1;"
                 :: "r"(m), "r"(bytes) : "memory");
}
__device__ __forceinline__ void mbar_wait(uint32_t m, uint32_t parity) {
    asm volatile(
        "{\n\t"
        ".reg .pred P;\n\t"
        "WL%=:\n\t"
        "mbarrier.try_wait.parity.acquire.cta.shared::cta.b64 P, [%0], %1, 0x989680;\n\t"
        "@P bra WD%=;\n\t"
        "bra WL%=;\n\t"
        "WD%=:\n\t"
        "}"
        :: "r"(m), "r"(parity) : "memory");
}
__device__ __forceinline__ uint32_t mapa_u32(uint32_t laddr, int rank) {
    uint32_t r;
    asm("mapa.shared::cluster.u32 %0, %1, %2;" : "=r"(r) : "r"(laddr), "r"(rank));
    return r;
}
__device__ __forceinline__ void st_async_b64(uint32_t raddr, u64 v, uint32_t rmbar) {
    asm volatile(
        "st.async.shared::cluster.mbarrier::complete_tx::bytes.b64 [%0], %1, [%2];"
        :: "r"(raddr), "l"(v), "r"(rmbar) : "memory");
}
// fast transcendentals (MUFU-based; rel err ~1e-6, far under 1e-3 budget)
__device__ __forceinline__ float fast_sig(float x) {
    return __fdividef(1.f, 1.f + __expf(-x));
}
__device__ __forceinline__ float fast_tanh(float x) {
    return 1.f - __fdividef(2.f, __expf(2.f * x) + 1.f);
}

// ---------------------------------------------------------------- k1: GEMM (R11, best)
__global__ __launch_bounds__(256, 2) void k1_gemm(const float* __restrict__ x,
                                                  const float* __restrict__ w,
                                                  const float* __restrict__ bias) {
    __shared__ __align__(16) float As[2][8][132];
    __shared__ __align__(16) float Bs[2][8][128];
    const int tid = threadIdx.x;
    const int n0 = blockIdx.x * 128, m0 = blockIdx.y * 128;
    const int tm = (tid >> 4) * 8, tn = (tid & 15) * 8;
    const int mA = tid >> 1, kq = (tid & 1) * 4;
    const int rB = tid >> 5, cB = (tid & 31) * 4;

    u64 acc2[4][8];
#pragma unroll
    for (int p = 0; p < 4; p++)
#pragma unroll
        for (int j = 0; j < 8; j++) acc2[p][j] = 0ull;

    float4 av = *reinterpret_cast<const float4*>(&x[(m0 + mA) * 256 + kq]);
    float4 bv = *reinterpret_cast<const float4*>(&w[rB * NG + n0 + cB]);

    for (int k0 = 0; k0 < 256; k0 += 8) {
        const int cur = (k0 >> 3) & 1;
        As[cur][kq + 0][mA] = av.x; As[cur][kq + 1][mA] = av.y;
        As[cur][kq + 2][mA] = av.z; As[cur][kq + 3][mA] = av.w;
        *reinterpret_cast<float4*>(&Bs[cur][rB][cB]) = bv;
        __syncthreads();
        if (k0 + 8 < 256) {
            av = *reinterpret_cast<const float4*>(&x[(m0 + mA) * 256 + k0 + 8 + kq]);
            bv = *reinterpret_cast<const float4*>(&w[(k0 + 8 + rB) * NG + n0 + cB]);
        }
#pragma unroll
        for (int k = 0; k < 8; k++) {
            const ulonglong2* ap = reinterpret_cast<const ulonglong2*>(&As[cur][k][tm]);
            const ulonglong2 aA = ap[0], aB = ap[1];
            const u64 a2[4] = {aA.x, aA.y, aB.x, aB.y};
            float b[8];
            *reinterpret_cast<float4*>(b)     = *reinterpret_cast<float4*>(&Bs[cur][k][tn]);
            *reinterpret_cast<float4*>(b + 4) = *reinterpret_cast<float4*>(&Bs[cur][k][tn + 4]);
            u64 b2[8];
#pragma unroll
            for (int j = 0; j < 8; j++) b2[j] = pack2(b[j], b[j]);
#pragma unroll
            for (int p = 0; p < 4; p++)
#pragma unroll
                for (int j = 0; j < 8; j++) acc2[p][j] = fma2(a2[p], b2[j], acc2[p][j]);
        }
    }
    float bi[8];
    *reinterpret_cast<float4*>(bi)     = *reinterpret_cast<const float4*>(&bias[n0 + tn]);
    *reinterpret_cast<float4*>(bi + 4) = *reinterpret_cast<const float4*>(&bias[n0 + tn + 4]);
#pragma unroll
    for (int p = 0; p < 4; p++) {
        float r0[8], r1[8];
#pragma unroll
        for (int j = 0; j < 8; j++) {
            float2 v = unpack2(acc2[p][j]);
            r0[j] = v.x + bi[j];
            r1[j] = v.y + bi[j];
        }
        float* d0 = &g_xz[(size_t)(m0 + tm + 2 * p) * NG + n0 + tn];
        float* d1 = d0 + NG;
#pragma unroll
        for (int j = 0; j < 8; j++) { d0[j] = r0[j]; d1[j] = r1[j]; }
    }
}

// ---------------------------------------------------------------- k2: sub-TKAN/KAN
// merged-s: one CTA per batch (128 CTAs = 1 wave), the 3 s-recurrences
// interleaved per thread (3x ILP in the serial chain, x loaded once).
__global__ __launch_bounds__(256) void k2_sub(const float* __restrict__ x,
                                              const float* __restrict__ stk,
                                              const float* __restrict__ srk,
                                              const float* __restrict__ kbw,
                                              const float* __restrict__ ksw) {
    __shared__ float sw[3][256 * 9];
    __shared__ float wpart[3][8];
    __shared__ float bc[3];
    const int b = blockIdx.x;
    const int d = threadIdx.x, lane = d & 31, wid = d >> 5;

    float skx[3], skh[3], bw[3], rh[3], rx[3];
#pragma unroll
    for (int s = 0; s < 3; s++) {
        skx[s] = srk[s * 512 + d];
        skh[s] = srk[s * 512 + 256 + d];
        bw[s]  = kbw[s * 256 + d];
        rh[s]  = stk[s * 2 + 0];
        rx[s]  = stk[s * 2 + 1];
#pragma unroll
        for (int c = 0; c < 8; c++) sw[s][d * 9 + c] = ksw[(s * 256 + d) * 8 + c];
    }
    __syncthreads();

    float sub[3] = {0.f, 0.f, 0.f};
    const float* xp = x + (b * T_) * D_ + d;

    float xv = __ldg(&xp[0]);
    for (int t = 0; t < T_; t++) {
        const float xn = (t < T_ - 1) ? __ldg(&xp[(t + 1) * D_]) : 0.f;
        float e[3];
#pragma unroll
        for (int s = 0; s < 3; s++) {
            const float v = xv * skx[s] + sub[s] * skh[s];
            float es = v * fast_sig(v) * bw[s];
            const float xg = (v + 2.2f) * 2.5f;
            const float fj = floorf(xg);
            const int j = (int)fj;
            if (j >= 0 && j <= 10) {
                const float wl = xg - fj, w2 = wl * wl, w3 = w2 * wl;
                const float omw = 1.f - wl;
                const float n0 = (1.f / 6.f) * omw * omw * omw;
                const float n1 = (1.f / 6.f) * (3.f * w3 - 6.f * w2 + 4.f);
                const float n2 = (1.f / 6.f) * (-3.f * w3 + 3.f * w2 + 3.f * wl + 1.f);
                const float n3 = (1.f / 6.f) * w3;
                const int c0 = j - 3;
                const float* swd = &sw[s][d * 9];
                if (c0     >= 0 && c0     < 8) es += n0 * swd[c0];
                if (c0 + 1 >= 0 && c0 + 1 < 8) es += n1 * swd[c0 + 1];
                if (c0 + 2 >= 0 && c0 + 2 < 8) es += n2 * swd[c0 + 2];
                if (c0 + 3 >= 0 && c0 + 3 < 8) es += n3 * swd[c0 + 3];
            }
            e[s] = es;
        }
#pragma unroll
        for (int off = 16; off > 0; off >>= 1) {
            e[0] += __shfl_xor_sync(0xffffffffu, e[0], off);
            e[1] += __shfl_xor_sync(0xffffffffu, e[1], off);
            e[2] += __shfl_xor_sync(0xffffffffu, e[2], off);
        }
        if (lane == 0) {
            wpart[0][wid] = e[0]; wpart[1][wid] = e[1]; wpart[2][wid] = e[2];
        }
        __syncthreads();
        if (d < 3) {   // thread s totals its own s in parallel
            float tot = 0.f;
#pragma unroll
            for (int ww = 0; ww < 8; ww++) tot += wpart[d][ww];
            g_subo[(d * B_ + b) * T_ + t] = tot;
            bc[d] = tot;
        }
        __syncthreads();
#pragma unroll
        for (int s = 0; s < 3; s++) sub[s] = rh[s] * bc[s] + rx[s] * sub[s];
        xv = xn;
    }
}

// ---------------------------------------------------------------- k3: recurrence
// 128 CTAs x 512 threads, cluster 8. Exchange/sync = R11 (best). NEW: warps
// 8-15 are couriers — they issue the gate-input LDGs (g_xz / g_subo) for step
// t+1 at the TOP of step t (latency hidden under compute) and deposit into
// double-buffered smem after S1. Gate warps' serial chain is now smem-only:
// DRAM latency AND its variance leave the cluster-wide max-of-8 step path.
__global__ __launch_bounds__(512, 1) __cluster_dims__(8, 1, 1)
void k3_rnn(const float* __restrict__ rk,   // (256,768)
            const float* __restrict__ aw,   // (3,256)
            const float* __restrict__ ab,   // (256)
            float* __restrict__ out) {      // (B,T,U)
    __shared__ __align__(16) float hs[2][2048];      // [buf][b_local*256 + u]
    __shared__ float red[256 * 51];                  // stride 51: conflict-free
    __shared__ float xzs[2][8][96];                  // [buf][b][gate*32 + u']
    __shared__ float sos[2][32];                     // [buf][s*8 + b]
    __shared__ __align__(8) unsigned long long mbar_s[2];
    const int tid = threadIdx.x;
    const int wid = tid >> 5, lane = tid & 31;
    const int u0 = (blockIdx.x & 7) * 32;
    const int b0 = (blockIdx.x >> 3) * 8;
    const int k0 = wid * 16;

    const uint32_t mb0 = smem_u32(&mbar_s[0]);
    const uint32_t mb1 = smem_u32(&mbar_s[1]);

    // weights: 16 k per warp, packed in pairs along k (once)
    u64 wi2[8], wf2[8], wc2[8];
#pragma unroll
    for (int kk = 0; kk < 8; kk++) {
        const int r0 = (k0 + 2 * kk) * NG + u0 + lane;
        const int r1 = r0 + NG;
        wi2[kk] = pack2(rk[r0],       rk[r1]);
        wf2[kk] = pack2(rk[r0 + 256], rk[r1 + 256]);
        wc2[kk] = pack2(rk[r0 + 512], rk[r1 + 512]);
    }
    // gate-role constants (warps 0-7): thread owns cell (b = b0+wid, u = u0+lane)
    const int gb = b0 + (wid & 7);
    const int gu = u0 + lane;
    const float aw0 = aw[gu], aw1 = aw[256 + gu], aw2 = aw[512 + gu];
    const float abr = ab[gu];
    float* yp = out + (size_t)(gb * T_) * U_ + gu;
    // courier-role constants (warps 8-15): warp handles batch cb = wid-8
    const int cb = wid & 7;
    const size_t cxbase = ((size_t)(b0 + cb) * T_) * NG + u0 + lane;

    // hoisted remote addresses (even lanes send b64 pairs) — R11
    uint32_t rh0[8], rm0[8];
    {
        const uint32_t lh = smem_u32(&hs[0][(wid & 7) * 256 + u0 + lane]);
#pragma unroll
        for (int r = 0; r < 8; r++) {
            rh0[r] = mapa_u32(lh, r);
            rm0[r] = mapa_u32(mb0, r);
        }
    }

    if (tid == 0) {
        mbar_init(mb0, 1);
        mbar_init(mb1, 1);
        mbar_arm(mb0, 8192);
        mbar_arm(mb1, 8192);
    }
    for (int i = tid; i < 2048; i += 512) hs[0][i] = 0.f;
    // prologue: couriers fill gate-input buffers for t=0
    if (wid >= 8) {
        xzs[0][cb][lane]      = __ldg(&g_xz[cxbase]);
        xzs[0][cb][32 + lane] = __ldg(&g_xz[cxbase + 256]);
        xzs[0][cb][64 + lane] = __ldg(&g_xz[cxbase + 512]);
        if (wid == 8 && lane < 24)
            sos[0][lane] = __ldg(&g_subo[((lane >> 3) * B_ + b0 + (lane & 7)) * T_]);
    }
    __syncthreads();
    asm volatile("barrier.cluster.arrive.aligned;\n\t"
                 "barrier.cluster.wait.aligned;" ::: "memory");

    float c = 0.f;
    for (int t = 0; t < T_; t++) {
        const int p = t & 1;
        if (t > 0) {
            const uint32_t m = p ? mb1 : mb0;
            mbar_wait(m, ((t - 1) >> 1) & 1);
            if (tid == 0) mbar_arm(m, 8192);   // re-arm for step t+1 sends
        }

        // couriers: issue LDGs for step t+1 NOW (hide DRAM under compute)
        float cx0, cx1, cx2, cs = 0.f;
        if (wid >= 8 && t < T_ - 1) {
            const size_t xo = cxbase + (size_t)(t + 1) * NG;
            cx0 = __ldg(&g_xz[xo]);
            cx1 = __ldg(&g_xz[xo + 256]);
            cx2 = __ldg(&g_xz[xo + 512]);
            if (wid == 8 && lane < 24)
                cs = __ldg(&g_subo[((lane >> 3) * B_ + b0 + (lane & 7)) * T_ + t + 1]);
        }

        // compute role: all 16 warps; h pairs from LDS.128 halves (broadcast)
#pragma unroll
        for (int b = 0; b < 8; b++) {
            u64 ai = 0ull, af = 0ull, ac = 0ull;
            const ulonglong2* hp =
                reinterpret_cast<const ulonglong2*>(&hs[p][b * 256 + k0]);
            const ulonglong2 h0 = hp[0], h1 = hp[1];
            ai = fma2(h0.x, wi2[0], ai); af = fma2(h0.x, wf2[0], af); ac = fma2(h0.x, wc2[0], ac);
            ai = fma2(h0.y, wi2[1], ai); af = fma2(h0.y, wf2[1], af); ac = fma2(h0.y, wc2[1], ac);
            ai = fma2(h1.x, wi2[2], ai); af = fma2(h1.x, wf2[2], af); ac = fma2(h1.x, wc2[2], ac);
            ai = fma2(h1.y, wi2[3], ai); af = fma2(h1.y, wf2[3], af); ac = fma2(h1.y, wc2[3], ac);
            const ulonglong2 h2 = hp[2], h3 = hp[3];
            ai = fma2(h2.x, wi2[4], ai); af = fma2(h2.x, wf2[4], af); ac = fma2(h2.x, wc2[4], ac);
            ai = fma2(h2.y, wi2[5], ai); af = fma2(h2.y, wf2[5], af); ac = fma2(h2.y, wc2[5], ac);
            ai = fma2(h3.x, wi2[6], ai); af = fma2(h3.x, wf2[6], af); ac = fma2(h3.x, wc2[6], ac);
            ai = fma2(h3.y, wi2[7], ai); af = fma2(h3.y, wf2[7], af); ac = fma2(h3.y, wc2[7], ac);
            const float2 vi = unpack2(ai), vf = unpack2(af), vc = unpack2(ac);
            const int base = (b * 32 + lane) * 51 + wid;   // 51 coprime w/ 32: conflict-free
            red[base]      = vi.x + vi.y;
            red[base + 16] = vf.x + vf.y;
            red[base + 32] = vc.x + vc.y;
        }
        __syncthreads();   // S1: red + gate-input buffers complete

        if (wid < 8) {
            // gate role: smem-only serial chain
            const float xz0 = xzs[p][wid][lane];
            const float xz1 = xzs[p][wid][32 + lane];
            const float xz2 = xzs[p][wid][64 + lane];
            const float o = fast_sig(sos[p][wid] * aw0 + sos[p][8 + wid] * aw1 +
                                     sos[p][16 + wid] * aw2 + abr);
            float zi = xz0, zf = xz1, zc = xz2;
            const int rbase = (wid * 32 + lane) * 51;
#pragma unroll
            for (int kg = 0; kg < 16; kg++) {
                zi += red[rbase + kg];
                zf += red[rbase + 16 + kg];
                zc += red[rbase + 32 + kg];
            }
            const float ig = fast_sig(zi);
            const float fg = fast_sig(zf);
            c = fg * c + ig * fast_tanh(zc);
            const float h = o * fast_tanh(c);

            // pair h values across adjacent lanes (full-warp shfl)
            const float hh = __shfl_down_sync(0xffffffffu, h, 1);
            if (t < T_ - 1 && !(lane & 1)) {
                const u64 hp2 = pack2(h, hh);
                const uint32_t hoff = p ? 0u : 8192u;   // target buffer hs[p^1]
                const uint32_t moff = p ? 0u : 8u;      // target mbar (mb0/mb1)
#pragma unroll
                for (int r = 0; r < 8; r++)
                    st_async_b64(rh0[r] + hoff, hp2, rm0[r] + moff);
            }
            yp[(size_t)t * U_] = h;
        } else if (t < T_ - 1) {
            // courier deposit for t+1 into the other parity buffer
            const int np = p ^ 1;
            xzs[np][cb][lane]      = cx0;
            xzs[np][cb][32 + lane] = cx1;
            xzs[np][cb][64 + lane] = cx2;
            if (wid == 8 && lane < 24) sos[np][lane] = cs;
        }
        // No S2 needed: local compute warps can only pass the t+1 mbar wait
        // after OUR OWN gate sends (self-rank tx), which follow all red reads;
        // courier deposits for t+1 are ordered before gate(t+1) reads by S1(t+1).
    }
    asm volatile("barrier.cluster.arrive.aligned;\n\t"
                 "barrier.cluster.wait.aligned;" ::: "memory");
}

// ---------------------------------------------------------------- launch
extern "C" void kernel_launch(void* const* d_in, const int* in_sizes, int n_in,
                              void* d_out, int out_size) {
    const float* x    = (const float*)d_in[0];
    const float* ker  = (const float*)d_in[1];
    const float* rk   = (const float*)d_in[2];
    const float* bias = (const float*)d_in[3];
    const float* stk  = (const float*)d_in[4];
    const float* srk  = (const float*)d_in[5];
    const float* aw   = (const float*)d_in[6];
    const float* ab   = (const float*)d_in[7];
    const float* kbw  = (const float*)d_in[8];
    const float* ksw  = (const float*)d_in[9];
    float* out = (float*)d_out;

    k1_gemm<<<dim3(NG / 128, M_ / 128), 256>>>(x, ker, bias);
    k2_sub<<<B_, 256>>>(x, stk, srk, kbw, ksw);
    k3_rnn<<<128, 512>>>(rk, aw, ab, out);
}